// round 9
// baseline (speedup 1.0000x reference)
#include <cuda_runtime.h>
#include <cuda_fp16.h>

// SparseConv1dNeq: fake-quant(in) -> masked sparse conv1d (fan-in 8, pad 1) -> fake-quant(out)
// x [512,64,1024] f32, weight [64,64,3] f32, mask [64,64,3] f32, out [512,64,1024] f32
//
// LSU-bound design: lane owns 4 positions; every tap = ONE LDS.64 (half4).
// Three shifted fp16 smem copies (A: k=1, B: k=0, C: k=2) keep all taps 8B-aligned.
// Tap tables packed 2 taps per uint4 -> one LDG.128 loads 2 taps.
// fp16 storage of quantized values is EXACT (<=8 significant bits) -> bitwise-equal math.

#define BATCH   512
#define IN_CH   64
#define OUT_CH  64
#define KW      3
#define LEN     1024
#define FAN_IN  8
#define TILE_T  128
#define NTHREADS 256

#define ROW_BYTES 256          // 128 halfs per row
#define A_BASE 0               // A[r][j] = x[t0+j],   j=0..127  (k=1)
#define B_BASE 16384           // B[r][j] = x[t0-1+j], j=0..127  (k=0)
#define C_BASE 32768           // C[r][j] = x[t0+1+j], j=0..127  (k=2)
#define SMEM_BYTES 49152       // exactly 48KB static

#define IN_SCALE_INV  16.0f
#define IN_SCALE      0.0625f
#define OUT_SCALE_INV 8.0f
#define OUT_SCALE     0.125f

// Packed taps: per out channel 4 x uint4 = {off0, w0bits, off1, w1bits} (byte offsets into smem)
__device__ uint4 g_tap[OUT_CH * FAN_IN / 2];

// ---------------- Prep: parallel ballot-based tap compaction ----------------
__global__ void prep_taps_kernel(const float* __restrict__ weight,
                                 const float* __restrict__ mask) {
    const int o   = blockIdx.x;
    const int idx = threadIdx.x;          // 0..191 over (ic*KW + k)
    __shared__ int wcnt[6];
    __shared__ int total;

    float m = mask[o * (IN_CH * KW) + idx];
    bool  p = (m != 0.0f);

    unsigned bal = __ballot_sync(0xffffffffu, p);
    int warp = idx >> 5;
    int lane = idx & 31;
    if (lane == 0) wcnt[warp] = __popc(bal);
    __syncthreads();

    int prefix = 0;
    #pragma unroll
    for (int w = 0; w < 6; w++)
        if (w < warp) prefix += wcnt[w];
    if (idx == 0) {
        int t = 0;
        #pragma unroll
        for (int w = 0; w < 6; w++) t += wcnt[w];
        total = t;
    }
    int rank = prefix + __popc(bal & ((1u << lane) - 1u));
    __syncthreads();

    int* gt = (int*)g_tap;
    if (p && rank < FAN_IN) {
        int ic = idx / KW;
        int k  = idx - ic * KW;
        int off;
        if (k == 0)      off = B_BASE + ic * ROW_BYTES;
        else if (k == 1) off = A_BASE + ic * ROW_BYTES;
        else             off = C_BASE + ic * ROW_BYTES;
        gt[(o * FAN_IN + rank) * 2]     = off;
        gt[(o * FAN_IN + rank) * 2 + 1] = __float_as_int(weight[o * (IN_CH * KW) + idx] * m);
    }
    if (idx < FAN_IN && idx >= total) {
        gt[(o * FAN_IN + idx) * 2]     = 0;     // points at A row 0; w=0 makes it harmless
        gt[(o * FAN_IN + idx) * 2 + 1] = 0;
    }
}

__device__ __forceinline__ float fq_in(float v) {
    return fminf(fmaxf(rintf(v * IN_SCALE_INV), -128.0f), 127.0f) * IN_SCALE;
}
__device__ __forceinline__ float fq_out(float v) {
    return fminf(fmaxf(rintf(v * OUT_SCALE_INV), -128.0f), 127.0f) * OUT_SCALE;
}
__device__ __forceinline__ unsigned pack2(float a, float b) {
    __half2 h = __floats2half2_rn(a, b);   // exact for quantized values
    return *reinterpret_cast<unsigned*>(&h);
}

// ---------------- Main kernel ----------------
__global__ __launch_bounds__(NTHREADS)
void sparse_conv1d_kernel(const float* __restrict__ x,
                          float* __restrict__ out) {
    __shared__ __align__(16) char xs[SMEM_BYTES];
    char* sp = xs;

    const int blk  = blockIdx.x;
    const int n    = blk >> 3;
    const int tile = blk & 7;
    const int t0   = tile * TILE_T;

    const float* xn = x + (size_t)n * IN_CH * LEN;
    const int tid  = threadIdx.x;
    const int lane = tid & 31;

    // ---- Load: each warp-iter covers one full row (32 lanes x 4 positions) ----
    #pragma unroll
    for (int it = 0; it < 8; it++) {
        const int r = (tid >> 5) + it * 8;
        const float4 q = __ldcs(reinterpret_cast<const float4*>(xn + r * LEN + t0 + (lane << 2)));
        float f0 = fq_in(q.x), f1 = fq_in(q.y), f2 = fq_in(q.z), f3 = fq_in(q.w);
        unsigned lo = pack2(f0, f1);            // (x[4l],   x[4l+1])
        unsigned hi = pack2(f2, f3);            // (x[4l+2], x[4l+3])
        char* rowp = sp + r * ROW_BYTES;

        // A: aligned half4 store
        *reinterpret_cast<uint2*>(rowp + A_BASE + (lane << 3)) = make_uint2(lo, hi);

        unsigned mid = __byte_perm(lo, hi, 0x5432);            // (x[4l+1], x[4l+2])
        unsigned nlo = __shfl_down_sync(0xffffffffu, lo, 1);   // next lane's (x[4l+4], x[4l+5])
        unsigned phi = __shfl_up_sync(0xffffffffu, hi, 1);     // prev lane's (x[4l-2], x[4l-1])

        // B[r][j] = x[t0-1+j]: word w holds (x[2w-1], x[2w])
        *reinterpret_cast<unsigned*>(rowp + B_BASE + (lane << 3) + 4) = mid;
        if (lane != 31)
            *reinterpret_cast<unsigned*>(rowp + B_BASE + (lane << 3) + 8) = __byte_perm(hi, nlo, 0x5432);

        // C[r][j] = x[t0+1+j]: word w holds (x[2w+1], x[2w+2])
        *reinterpret_cast<unsigned*>(rowp + C_BASE + (lane << 3)) = mid;
        if (lane != 0)
            *reinterpret_cast<unsigned*>(rowp + C_BASE + (lane << 3) - 4) = __byte_perm(phi, lo, 0x5432);
    }
    // ---- Halos: B word 0 (x[-1], x[0]) and C word 63 (x[127], x[128]) per row ----
    if (tid < IN_CH) {
        int r = tid;
        float a = (t0 > 0) ? fq_in(xn[r * LEN + t0 - 1]) : 0.0f;
        float b = fq_in(xn[r * LEN + t0]);
        *reinterpret_cast<unsigned*>(sp + B_BASE + r * ROW_BYTES) = pack2(a, b);
    } else if (tid >= 128 && tid < 128 + IN_CH) {
        int r = tid - 128;
        float a = fq_in(xn[r * LEN + t0 + TILE_T - 1]);
        float b = (t0 + TILE_T < LEN) ? fq_in(xn[r * LEN + t0 + TILE_T]) : 0.0f;
        *reinterpret_cast<unsigned*>(sp + C_BASE + r * ROW_BYTES + 252) = pack2(a, b);
    }
    __syncthreads();

    // ---- Compute: warp w -> channels [w*8, w*8+8); lane -> positions 4l..4l+3 ----
    const int warp = tid >> 5;
    float* outn = out + (size_t)n * OUT_CH * LEN + t0;
    const int lb = lane << 3;   // byte offset of this lane's half4 within a row copy

    #pragma unroll 1
    for (int oi = 0; oi < 8; oi++) {
        const int o = warp * 8 + oi;
        const uint4* taps = g_tap + o * (FAN_IN / 2);

        float a0 = 0.f, a1 = 0.f, a2 = 0.f, a3 = 0.f;
        float b0 = 0.f, b1 = 0.f, b2 = 0.f, b3 = 0.f;

        #pragma unroll
        for (int p = 0; p < FAN_IN / 2; p++) {
            const uint4 tp = taps[p];   // {off0, w0, off1, w1} — one LDG.128, 2 taps

            uint2 qa = *reinterpret_cast<const uint2*>(sp + tp.x + lb);
            float2 ua = __half22float2(*reinterpret_cast<__half2*>(&qa.x));
            float2 va = __half22float2(*reinterpret_cast<__half2*>(&qa.y));
            float wa = __int_as_float((int)tp.y);
            a0 = fmaf(wa, ua.x, a0); a1 = fmaf(wa, ua.y, a1);
            a2 = fmaf(wa, va.x, a2); a3 = fmaf(wa, va.y, a3);

            uint2 qb = *reinterpret_cast<const uint2*>(sp + tp.z + lb);
            float2 ub = __half22float2(*reinterpret_cast<__half2*>(&qb.x));
            float2 vb = __half22float2(*reinterpret_cast<__half2*>(&qb.y));
            float wb = __int_as_float((int)tp.w);
            b0 = fmaf(wb, ub.x, b0); b1 = fmaf(wb, ub.y, b1);
            b2 = fmaf(wb, vb.x, b2); b3 = fmaf(wb, vb.y, b3);
        }

        float4 res;
        res.x = fq_out(a0 + b0);
        res.y = fq_out(a1 + b1);
        res.z = fq_out(a2 + b2);
        res.w = fq_out(a3 + b3);
        __stcs(reinterpret_cast<float4*>(outn + (size_t)o * LEN + (lane << 2)), res);
    }
}

extern "C" void kernel_launch(void* const* d_in, const int* in_sizes, int n_in,
                              void* d_out, int out_size) {
    const float* x      = (const float*)d_in[0];
    const float* weight = (const float*)d_in[1];
    const float* mask   = (const float*)d_in[2];
    float*       out    = (float*)d_out;

    prep_taps_kernel<<<OUT_CH, IN_CH * KW>>>(weight, mask);
    sparse_conv1d_kernel<<<BATCH * (LEN / TILE_T), NTHREADS>>>(x, out);
}